// round 2
// baseline (speedup 1.0000x reference)
#include <cuda_runtime.h>
#include <math.h>

#define BB 2
#define NN 1024
#define HH 128
#define WW 128
#define CHUNK 128

// Scratch (no allocations allowed)
__device__ float4 d_sorted[BB * NN * 3];          // per gaussian: [px,py,h00,h01][h11,op,r,g][b,z,-,-]
__device__ float  d_rgb[BB * 3 * HH * WW];        // rendered rgb (clipped)
__device__ double d_acc[4];                       // l1_rgb_sum, l1_depth_sum, ssim_sum, opac_sum

__device__ __forceinline__ float warp_sum(float v) {
#pragma unroll
    for (int o = 16; o; o >>= 1) v += __shfl_down_sync(0xffffffffu, v, o);
    return v;
}

__global__ void zero_kernel() {
    if (threadIdx.x < 4) d_acc[threadIdx.x] = 0.0;
}

// One block per batch, 1024 threads = 1 gaussian each.
__global__ void prep_kernel(const float* __restrict__ g, const float* __restrict__ intr) {
    int b = blockIdx.x;
    int i = threadIdx.x;
    const float* gg = g + ((size_t)b * NN + i) * 38;
    float m0 = gg[0], m1 = gg[1], m2 = gg[2];
    float sx = gg[3], sy = gg[4], sz = gg[5];
    float qw = gg[6], qx = gg[7], qy = gg[8], qz = gg[9];
    float op = gg[10];
    float shr = gg[11], shg = gg[12], shb = gg[13];
    const float* I = intr + b * 9;
    float fx = I[0], cx = I[2], fy = I[4], cy = I[5];

    float zz = fmaxf(m2, 1e-4f);
    float px = fx * m0 / zz + cx;
    float py = fy * m1 / zz + cy;

    // quaternion -> rotation
    float R00 = 1.f - 2.f * (qy * qy + qz * qz), R01 = 2.f * (qx * qy - qw * qz), R02 = 2.f * (qx * qz + qw * qy);
    float R10 = 2.f * (qx * qy + qw * qz), R11 = 1.f - 2.f * (qx * qx + qz * qz), R12 = 2.f * (qy * qz - qw * qx);
    float R20 = 2.f * (qx * qz - qw * qy), R21 = 2.f * (qy * qz + qw * qx), R22 = 1.f - 2.f * (qx * qx + qy * qy);
    // RS = R * diag(scales) (column scaling)
    float A00 = R00 * sx, A01 = R01 * sy, A02 = R02 * sz;
    float A10 = R10 * sx, A11 = R11 * sy, A12 = R12 * sz;
    float A20 = R20 * sx, A21 = R21 * sy, A22 = R22 * sz;
    // cov3d = A A^T (symmetric)
    float C00 = A00 * A00 + A01 * A01 + A02 * A02;
    float C01 = A00 * A10 + A01 * A11 + A02 * A12;
    float C02 = A00 * A20 + A01 * A21 + A02 * A22;
    float C11 = A10 * A10 + A11 * A11 + A12 * A12;
    float C12 = A10 * A20 + A11 * A21 + A12 * A22;
    float C22 = A20 * A20 + A21 * A21 + A22 * A22;

    float zc = fmaxf(m2, 1e-6f);
    float zi = 1.f / zc, zi2 = zi * zi;
    float J00 = fx * zi, J02 = -fx * m0 * zi2;
    float J11 = fy * zi, J12 = -fy * m1 * zi2;
    // t = row0(J)*C, u = row1(J)*C   (C symmetric)
    float t0 = J00 * C00 + J02 * C02;
    float t1 = J00 * C01 + J02 * C12;
    float t2 = J00 * C02 + J02 * C22;
    float u0 = J11 * C01 + J12 * C02;
    float u1 = J11 * C11 + J12 * C12;
    float u2 = J11 * C12 + J12 * C22;
    float c00 = t0 * J00 + t2 * J02 + 0.3f;
    float c01 = t1 * J11 + t2 * J12;
    float c10 = u0 * J00 + u2 * J02;
    float c11 = u1 * J11 + u2 * J12 + 0.3f;
    float det = fmaxf(c00 * c11 - c01 * c10, 1e-8f);
    float inv00 = c11 / det, inv11 = c00 / det, inv01 = -c01 / det;

    const float C0c = 0.28209479177387814f;
    float cr = fminf(fmaxf(shr * C0c + 0.5f, 0.f), 1.f);
    float cg = fminf(fmaxf(shg * C0c + 0.5f, 0.f), 1.f);
    float cb = fminf(fmaxf(shb * C0c + 0.5f, 0.f), 1.f);

    // stable rank by z (matches jnp.argsort stable semantics)
    __shared__ float zbuf[NN];
    zbuf[i] = zz;
    __syncthreads();
    int rank = 0;
#pragma unroll 8
    for (int j = 0; j < NN; j++) {
        float zj = zbuf[j];
        rank += (zj < zz) || (zj == zz && j < i);
    }
    // store negated half-precision-free quadratic coefficients:
    // power = h00*dx*dx + h01*dx*dy + h11*dy*dy  (h's absorb the -0.5 factor)
    float4* dst = d_sorted + (b * NN + rank) * 3;
    dst[0] = make_float4(px, py, -0.5f * inv00, -inv01);
    dst[1] = make_float4(-0.5f * inv11, op, cr, cg);
    dst[2] = make_float4(cb, zz, 0.f, 0.f);

    // opacity entropy regularizer
    float o = fminf(fmaxf(op, 1e-6f), 1.f - 1e-6f);
    float ent = -(o * logf(o) + (1.f - o) * logf(1.f - o));

    __shared__ float red[32];
    float v = warp_sum(ent);
    int lane = i & 31, wid = i >> 5;
    if (lane == 0) red[wid] = v;
    __syncthreads();
    if (wid == 0) {
        float x = (lane < 32) ? red[lane] : 0.f;
        x = warp_sum(x);
        if (lane == 0) atomicAdd(&d_acc[3], (double)x);
    }
}

// 16x16 pixel tile per block; grid (W/16, H/16, B)
__global__ void render_kernel(const float* __restrict__ target_rgb,
                              const float* __restrict__ target_depth) {
    int b = blockIdx.z;
    int x = blockIdx.x * 16 + threadIdx.x;
    int y = blockIdx.y * 16 + threadIdx.y;
    int tid = threadIdx.y * 16 + threadIdx.x;
    float xf = (float)x, yf = (float)y;

    __shared__ float4 sg[CHUNK * 3];
    const float4* base = d_sorted + b * NN * 3;

    float T = 1.f, aR = 0.f, aG = 0.f, aB = 0.f, aD = 0.f;

    for (int c0 = 0; c0 < NN; c0 += CHUNK) {
        __syncthreads();
        for (int k = tid; k < CHUNK * 3; k += 256) sg[k] = base[c0 * 3 + k];
        __syncthreads();
#pragma unroll 4
        for (int j = 0; j < CHUNK; j++) {
            float4 p0 = sg[j * 3 + 0];
            float4 p1 = sg[j * 3 + 1];
            float4 p2 = sg[j * 3 + 2];
            float dx = xf - p0.x;
            float dy = yf - p0.y;
            float pw = (p0.z * dx + p0.w * dy) * dx + p1.x * dy * dy;
            pw = fminf(fmaxf(pw, -10.f), 0.f);
            float a = __expf(pw) * p1.y;
            a = fminf(a, 0.99f);
            float w = T * a;
            aR += w * p1.z;
            aG += w * p1.w;
            aB += w * p2.x;
            aD += w * p2.y;
            T *= (1.f - a);
        }
    }
    aR = fminf(fmaxf(aR, 0.f), 1.f);
    aG = fminf(fmaxf(aG, 0.f), 1.f);
    aB = fminf(fmaxf(aB, 0.f), 1.f);

    int hw = HH * WW;
    int pix = y * WW + x;
    d_rgb[(b * 3 + 0) * hw + pix] = aR;
    d_rgb[(b * 3 + 1) * hw + pix] = aG;
    d_rgb[(b * 3 + 2) * hw + pix] = aB;

    float l1 = fabsf(aR - target_rgb[(b * 3 + 0) * hw + pix]) +
               fabsf(aG - target_rgb[(b * 3 + 1) * hw + pix]) +
               fabsf(aB - target_rgb[(b * 3 + 2) * hw + pix]);
    float l1d = fabsf(aD - target_depth[b * hw + pix]);

    __shared__ float red[8];
    int lane = tid & 31, wid = tid >> 5;
    float v = warp_sum(l1);
    if (lane == 0) red[wid] = v;
    __syncthreads();
    if (wid == 0) {
        float s = (lane < 8) ? red[lane] : 0.f;
        s = warp_sum(s);
        if (lane == 0) atomicAdd(&d_acc[0], (double)s);
    }
    __syncthreads();
    v = warp_sum(l1d);
    if (lane == 0) red[wid] = v;
    __syncthreads();
    if (wid == 0) {
        float s = (lane < 8) ? red[lane] : 0.f;
        s = warp_sum(s);
        if (lane == 0) atomicAdd(&d_acc[1], (double)s);
    }
}

// one thread per (b, c, y, x): fused 7x7 depthwise SSIM + mean reduce
__global__ void ssim_kernel(const float* __restrict__ target_rgb) {
    int idx = blockIdx.x * 256 + threadIdx.x;
    float val = 0.f;
    if (idx < BB * 3 * HH * WW) {
        int x = idx % WW;
        int y = (idx / WW) % HH;
        int bc = idx / (HH * WW);

        // normalized 1D gaussian window (size 7, sigma 1.5)
        float gw[7];
        float s = 0.f;
#pragma unroll
        for (int k = 0; k < 7; k++) {
            float c = (float)(k - 3);
            gw[k] = __expf(-c * c / 4.5f);
            s += gw[k];
        }
        float inv = 1.f / s;
#pragma unroll
        for (int k = 0; k < 7; k++) gw[k] *= inv;

        const float* i1 = d_rgb + (size_t)bc * HH * WW;
        const float* i2 = target_rgb + (size_t)bc * HH * WW;

        float m1 = 0.f, m2 = 0.f, e11 = 0.f, e22 = 0.f, e12 = 0.f;
#pragma unroll
        for (int ky = 0; ky < 7; ky++) {
            int yy = y + ky - 3;
            if (yy < 0 || yy >= HH) continue;
            float wy = gw[ky];
#pragma unroll
            for (int kx = 0; kx < 7; kx++) {
                int xx = x + kx - 3;
                if (xx < 0 || xx >= WW) continue;
                float w = wy * gw[kx];
                float v1 = i1[yy * WW + xx];
                float v2 = i2[yy * WW + xx];
                m1 += w * v1;
                m2 += w * v2;
                e11 += w * v1 * v1;
                e22 += w * v2 * v2;
                e12 += w * v1 * v2;
            }
        }
        float s1 = e11 - m1 * m1;
        float s2 = e22 - m2 * m2;
        float s12 = e12 - m1 * m2;
        const float C1 = 0.0001f, C2 = 0.0009f;
        val = (2.f * m1 * m2 + C1) * (2.f * s12 + C2) /
              ((m1 * m1 + m2 * m2 + C1) * (s1 + s2 + C2));
    }
    __shared__ float red[8];
    int lane = threadIdx.x & 31, wid = threadIdx.x >> 5;
    float v = warp_sum(val);
    if (lane == 0) red[wid] = v;
    __syncthreads();
    if (wid == 0) {
        float x2 = (lane < 8) ? red[lane] : 0.f;
        x2 = warp_sum(x2);
        if (lane == 0) atomicAdd(&d_acc[2], (double)x2);
    }
}

__global__ void final_kernel(float* __restrict__ out) {
    double l1rgb = d_acc[0] / (double)(BB * 3 * HH * WW);
    double l1d = d_acc[1] / (double)(BB * HH * WW);
    double ssim = d_acc[2] / (double)(BB * 3 * HH * WW);
    double opac = d_acc[3] / (double)(BB * NN);
    out[0] = (float)(0.8 * l1rgb + 0.2 * (1.0 - ssim) + 0.5 * l1d + 0.01 * opac);
}

extern "C" void kernel_launch(void* const* d_in, const int* in_sizes, int n_in,
                              void* d_out, int out_size) {
    const float* gaussians = (const float*)d_in[0];
    const float* intrinsics = (const float*)d_in[1];
    const float* target_rgb = (const float*)d_in[2];
    const float* target_depth = (const float*)d_in[3];
    float* out = (float*)d_out;

    zero_kernel<<<1, 32>>>();
    prep_kernel<<<BB, NN>>>(gaussians, intrinsics);
    render_kernel<<<dim3(WW / 16, HH / 16, BB), dim3(16, 16)>>>(target_rgb, target_depth);
    ssim_kernel<<<(BB * 3 * HH * WW + 255) / 256, 256>>>(target_rgb);
    final_kernel<<<1, 1>>>(out);
}

// round 3
// speedup vs baseline: 1.3208x; 1.3208x over previous
#include <cuda_runtime.h>
#include <math.h>

#define BB 2
#define NN 1024
#define HH 128
#define WW 128
#define SEG 8
#define GPS (NN / SEG)   // gaussians per segment = 128

// Scratch (static device globals — allowed)
__device__ float4 d_sorted[BB * NN * 3];            // [px,py,h00,h01][h11,op,r,g][b,z,-,-]
__device__ float4 d_seg_rgbd[BB * SEG * HH * WW];   // per-segment partial RGBD
__device__ float  d_seg_T[BB * SEG * HH * WW];      // per-segment transmittance
__device__ float  d_rgb[BB * 3 * HH * WW];          // final rgb (clipped)
__device__ double d_acc[4];                         // l1_rgb, l1_depth, ssim, opac sums

__device__ __forceinline__ float warp_sum(float v) {
#pragma unroll
    for (int o = 16; o; o >>= 1) v += __shfl_down_sync(0xffffffffu, v, o);
    return v;
}

__global__ void zero_kernel() {
    if (threadIdx.x < 4) d_acc[threadIdx.x] = 0.0;
}

// One block per batch, 1024 threads = 1 gaussian each.
__global__ void prep_kernel(const float* __restrict__ g, const float* __restrict__ intr) {
    int b = blockIdx.x;
    int i = threadIdx.x;
    const float* gg = g + ((size_t)b * NN + i) * 38;
    float m0 = gg[0], m1 = gg[1], m2 = gg[2];
    float sx = gg[3], sy = gg[4], sz = gg[5];
    float qw = gg[6], qx = gg[7], qy = gg[8], qz = gg[9];
    float op = gg[10];
    float shr = gg[11], shg = gg[12], shb = gg[13];
    const float* I = intr + b * 9;
    float fx = I[0], cx = I[2], fy = I[4], cy = I[5];

    float zz = fmaxf(m2, 1e-4f);
    float px = fx * m0 / zz + cx;
    float py = fy * m1 / zz + cy;

    // quaternion -> rotation
    float R00 = 1.f - 2.f * (qy * qy + qz * qz), R01 = 2.f * (qx * qy - qw * qz), R02 = 2.f * (qx * qz + qw * qy);
    float R10 = 2.f * (qx * qy + qw * qz), R11 = 1.f - 2.f * (qx * qx + qz * qz), R12 = 2.f * (qy * qz - qw * qx);
    float R20 = 2.f * (qx * qz - qw * qy), R21 = 2.f * (qy * qz + qw * qx), R22 = 1.f - 2.f * (qx * qx + qy * qy);
    float A00 = R00 * sx, A01 = R01 * sy, A02 = R02 * sz;
    float A10 = R10 * sx, A11 = R11 * sy, A12 = R12 * sz;
    float A20 = R20 * sx, A21 = R21 * sy, A22 = R22 * sz;
    float C00 = A00 * A00 + A01 * A01 + A02 * A02;
    float C01 = A00 * A10 + A01 * A11 + A02 * A12;
    float C02 = A00 * A20 + A01 * A21 + A02 * A22;
    float C11 = A10 * A10 + A11 * A11 + A12 * A12;
    float C12 = A10 * A20 + A11 * A21 + A12 * A22;
    float C22 = A20 * A20 + A21 * A21 + A22 * A22;

    float zc = fmaxf(m2, 1e-6f);
    float zi = 1.f / zc, zi2 = zi * zi;
    float J00 = fx * zi, J02 = -fx * m0 * zi2;
    float J11 = fy * zi, J12 = -fy * m1 * zi2;
    float t0 = J00 * C00 + J02 * C02;
    float t1 = J00 * C01 + J02 * C12;
    float t2 = J00 * C02 + J02 * C22;
    float u0 = J11 * C01 + J12 * C02;
    float u1 = J11 * C11 + J12 * C12;
    float u2 = J11 * C12 + J12 * C22;
    float c00 = t0 * J00 + t2 * J02 + 0.3f;
    float c01 = t1 * J11 + t2 * J12;
    float c10 = u0 * J00 + u2 * J02;
    float c11 = u1 * J11 + u2 * J12 + 0.3f;
    float det = fmaxf(c00 * c11 - c01 * c10, 1e-8f);
    float inv00 = c11 / det, inv11 = c00 / det, inv01 = -c01 / det;

    const float C0c = 0.28209479177387814f;
    float cr = fminf(fmaxf(shr * C0c + 0.5f, 0.f), 1.f);
    float cg = fminf(fmaxf(shg * C0c + 0.5f, 0.f), 1.f);
    float cb = fminf(fmaxf(shb * C0c + 0.5f, 0.f), 1.f);

    // stable rank by z (matches jnp.argsort stable semantics)
    __shared__ float zbuf[NN];
    zbuf[i] = zz;
    __syncthreads();
    int rank = 0;
#pragma unroll 8
    for (int j = 0; j < NN; j++) {
        float zj = zbuf[j];
        rank += (zj < zz) || (zj == zz && j < i);
    }
    // conic pre-scaled by log2(e); pw in log2 domain:
    // pw = h00*dx^2 + h01*dx*dy + h11*dy^2   (clamped to [-10*log2e, 0], then ex2)
    const float L2E = 1.4426950408889634f;
    float4* dst = d_sorted + (b * NN + rank) * 3;
    dst[0] = make_float4(px, py, -0.5f * inv00 * L2E, -inv01 * L2E);
    dst[1] = make_float4(-0.5f * inv11 * L2E, op, cr, cg);
    dst[2] = make_float4(cb, zz, 0.f, 0.f);

    float o = fminf(fmaxf(op, 1e-6f), 1.f - 1e-6f);
    float ent = -(o * logf(o) + (1.f - o) * logf(1.f - o));

    __shared__ float red[32];
    float v = warp_sum(ent);
    int lane = i & 31, wid = i >> 5;
    if (lane == 0) red[wid] = v;
    __syncthreads();
    if (wid == 0) {
        float x = (lane < 32) ? red[lane] : 0.f;
        x = warp_sum(x);
        if (lane == 0) atomicAdd(&d_acc[3], (double)x);
    }
}

// grid (W/16, H/16, B*SEG); each block composites one 128-gaussian depth segment
// over a 16x16 pixel tile and writes partial (RGBD, T).
__global__ void render_kernel() {
    int bz = blockIdx.z;
    int b = bz >> 3;       // SEG == 8
    int s = bz & 7;
    int x = blockIdx.x * 16 + threadIdx.x;
    int y = blockIdx.y * 16 + threadIdx.y;
    int tid = threadIdx.y * 16 + threadIdx.x;
    float xf = (float)x, yf = (float)y;

    __shared__ float4 sg[GPS * 3];
    const float4* base = d_sorted + (b * NN + s * GPS) * 3;
    for (int k = tid; k < GPS * 3; k += 256) sg[k] = base[k];
    __syncthreads();

    float T = 1.f, aR = 0.f, aG = 0.f, aB = 0.f, aD = 0.f;
#pragma unroll 4
    for (int j = 0; j < GPS; j++) {
        float4 p0 = sg[j * 3 + 0];
        float4 p1 = sg[j * 3 + 1];
        float4 p2 = sg[j * 3 + 2];
        float dx = xf - p0.x;
        float dy = yf - p0.y;
        float u = fmaf(p0.z, dx, p0.w * dy);
        float pw = fmaf(dx, u, p1.x * dy * dy);
        pw = fminf(fmaxf(pw, -14.4269504088896f), 0.f);
        float e;
        asm("ex2.approx.f32 %0, %1;" : "=f"(e) : "f"(pw));
        float a = fminf(e * p1.y, 0.99f);
        float w = T * a;
        aR = fmaf(w, p1.z, aR);
        aG = fmaf(w, p1.w, aG);
        aB = fmaf(w, p2.x, aB);
        aD = fmaf(w, p2.y, aD);
        T = fmaf(-a, T, T);
    }
    int o = (b * SEG + s) * (HH * WW) + y * WW + x;
    d_seg_rgbd[o] = make_float4(aR, aG, aB, aD);
    d_seg_T[o] = T;
}

// Combine SEG partials per pixel front-to-back; write rgb; L1 reductions.
__global__ void merge_kernel(const float* __restrict__ target_rgb,
                             const float* __restrict__ target_depth) {
    int idx = blockIdx.x * 256 + threadIdx.x;
    int hw = HH * WW;
    int b = idx / hw;
    int pix = idx % hw;

    float T = 1.f, R = 0.f, G = 0.f, Bc = 0.f, D = 0.f;
#pragma unroll
    for (int s = 0; s < SEG; s++) {
        int o = (b * SEG + s) * hw + pix;
        float4 c = d_seg_rgbd[o];
        float t = d_seg_T[o];
        R = fmaf(T, c.x, R);
        G = fmaf(T, c.y, G);
        Bc = fmaf(T, c.z, Bc);
        D = fmaf(T, c.w, D);
        T *= t;
    }
    R = fminf(fmaxf(R, 0.f), 1.f);
    G = fminf(fmaxf(G, 0.f), 1.f);
    Bc = fminf(fmaxf(Bc, 0.f), 1.f);

    d_rgb[(b * 3 + 0) * hw + pix] = R;
    d_rgb[(b * 3 + 1) * hw + pix] = G;
    d_rgb[(b * 3 + 2) * hw + pix] = Bc;

    float l1 = fabsf(R - target_rgb[(b * 3 + 0) * hw + pix]) +
               fabsf(G - target_rgb[(b * 3 + 1) * hw + pix]) +
               fabsf(Bc - target_rgb[(b * 3 + 2) * hw + pix]);
    float l1d = fabsf(D - target_depth[b * hw + pix]);

    __shared__ float red[8];
    int lane = threadIdx.x & 31, wid = threadIdx.x >> 5;
    float v = warp_sum(l1);
    if (lane == 0) red[wid] = v;
    __syncthreads();
    if (wid == 0) {
        float sm = (lane < 8) ? red[lane] : 0.f;
        sm = warp_sum(sm);
        if (lane == 0) atomicAdd(&d_acc[0], (double)sm);
    }
    __syncthreads();
    v = warp_sum(l1d);
    if (lane == 0) red[wid] = v;
    __syncthreads();
    if (wid == 0) {
        float sm = (lane < 8) ? red[lane] : 0.f;
        sm = warp_sum(sm);
        if (lane == 0) atomicAdd(&d_acc[1], (double)sm);
    }
}

// fused 7x7 depthwise SSIM + mean reduce; constant weights, interior fast path
__global__ void ssim_kernel(const float* __restrict__ target_rgb) {
    const float GW[7] = {0.03663229f, 0.11128005f, 0.21674607f, 0.27068313f,
                         0.21674607f, 0.11128005f, 0.03663229f};
    int idx = blockIdx.x * 256 + threadIdx.x;
    float val = 0.f;
    if (idx < BB * 3 * HH * WW) {
        int x = idx % WW;
        int y = (idx / WW) % HH;
        int bc = idx / (HH * WW);
        const float* i1 = d_rgb + (size_t)bc * HH * WW;
        const float* i2 = target_rgb + (size_t)bc * HH * WW;

        float m1 = 0.f, m2 = 0.f, e11 = 0.f, e22 = 0.f, e12 = 0.f;
        if (x >= 3 && x < WW - 3 && y >= 3 && y < HH - 3) {
#pragma unroll
            for (int ky = 0; ky < 7; ky++) {
                int yy = y + ky - 3;
                float wy = GW[ky];
#pragma unroll
                for (int kx = 0; kx < 7; kx++) {
                    int xx = x + kx - 3;
                    float w = wy * GW[kx];
                    float v1 = i1[yy * WW + xx];
                    float v2 = i2[yy * WW + xx];
                    m1 = fmaf(w, v1, m1);
                    m2 = fmaf(w, v2, m2);
                    e11 = fmaf(w * v1, v1, e11);
                    e22 = fmaf(w * v2, v2, e22);
                    e12 = fmaf(w * v1, v2, e12);
                }
            }
        } else {
#pragma unroll
            for (int ky = 0; ky < 7; ky++) {
                int yy = y + ky - 3;
                if (yy < 0 || yy >= HH) continue;
                float wy = GW[ky];
#pragma unroll
                for (int kx = 0; kx < 7; kx++) {
                    int xx = x + kx - 3;
                    if (xx < 0 || xx >= WW) continue;
                    float w = wy * GW[kx];
                    float v1 = i1[yy * WW + xx];
                    float v2 = i2[yy * WW + xx];
                    m1 = fmaf(w, v1, m1);
                    m2 = fmaf(w, v2, m2);
                    e11 = fmaf(w * v1, v1, e11);
                    e22 = fmaf(w * v2, v2, e22);
                    e12 = fmaf(w * v1, v2, e12);
                }
            }
        }
        float s1 = e11 - m1 * m1;
        float s2 = e22 - m2 * m2;
        float s12 = e12 - m1 * m2;
        const float C1 = 0.0001f, C2 = 0.0009f;
        val = (2.f * m1 * m2 + C1) * (2.f * s12 + C2) /
              ((m1 * m1 + m2 * m2 + C1) * (s1 + s2 + C2));
    }
    __shared__ float red[8];
    int lane = threadIdx.x & 31, wid = threadIdx.x >> 5;
    float v = warp_sum(val);
    if (lane == 0) red[wid] = v;
    __syncthreads();
    if (wid == 0) {
        float x2 = (lane < 8) ? red[lane] : 0.f;
        x2 = warp_sum(x2);
        if (lane == 0) atomicAdd(&d_acc[2], (double)x2);
    }
}

__global__ void final_kernel(float* __restrict__ out) {
    double l1rgb = d_acc[0] / (double)(BB * 3 * HH * WW);
    double l1d = d_acc[1] / (double)(BB * HH * WW);
    double ssim = d_acc[2] / (double)(BB * 3 * HH * WW);
    double opac = d_acc[3] / (double)(BB * NN);
    out[0] = (float)(0.8 * l1rgb + 0.2 * (1.0 - ssim) + 0.5 * l1d + 0.01 * opac);
}

extern "C" void kernel_launch(void* const* d_in, const int* in_sizes, int n_in,
                              void* d_out, int out_size) {
    const float* gaussians = (const float*)d_in[0];
    const float* intrinsics = (const float*)d_in[1];
    const float* target_rgb = (const float*)d_in[2];
    const float* target_depth = (const float*)d_in[3];
    float* out = (float*)d_out;

    zero_kernel<<<1, 32>>>();
    prep_kernel<<<BB, NN>>>(gaussians, intrinsics);
    render_kernel<<<dim3(WW / 16, HH / 16, BB * SEG), dim3(16, 16)>>>();
    merge_kernel<<<(BB * HH * WW) / 256, 256>>>(target_rgb, target_depth);
    ssim_kernel<<<(BB * 3 * HH * WW + 255) / 256, 256>>>(target_rgb);
    final_kernel<<<1, 1>>>(out);
}

// round 4
// speedup vs baseline: 1.9961x; 1.5113x over previous
#include <cuda_runtime.h>
#include <math.h>

#define BB 2
#define NN 1024
#define HH 128
#define WW 128
#define SEG 8
#define GPS (NN / SEG)   // gaussians per segment = 128

typedef unsigned long long u64;

// Scratch (static device globals — allowed)
__device__ float4 d_attr[BB * NN * 3];              // unsorted attrs
__device__ float  d_z[BB * NN];
__device__ float4 d_sorted[BB * NN * 3];            // [npx,npy,h00,h01][h11,op,r,g][b,z,-,-]
__device__ float4 d_seg_rgbd[BB * SEG * HH * WW];
__device__ float  d_seg_T[BB * SEG * HH * WW];
__device__ float  d_rgb[BB * 3 * HH * WW];
__device__ double d_acc[4];                         // l1_rgb, l1_depth, ssim, opac

__device__ __forceinline__ float warp_sum(float v) {
#pragma unroll
    for (int o = 16; o; o >>= 1) v += __shfl_down_sync(0xffffffffu, v, o);
    return v;
}

// ---- packed f32x2 helpers ----
__device__ __forceinline__ u64 pk2(float lo, float hi) {
    u64 r; asm("mov.b64 %0, {%1, %2};" : "=l"(r) : "f"(lo), "f"(hi)); return r;
}
__device__ __forceinline__ void upk2(float& lo, float& hi, u64 v) {
    asm("mov.b64 {%0, %1}, %2;" : "=f"(lo), "=f"(hi) : "l"(v));
}
__device__ __forceinline__ u64 add2(u64 a, u64 b) {
    u64 r; asm("add.rn.f32x2 %0, %1, %2;" : "=l"(r) : "l"(a), "l"(b)); return r;
}
__device__ __forceinline__ u64 mul2(u64 a, u64 b) {
    u64 r; asm("mul.rn.f32x2 %0, %1, %2;" : "=l"(r) : "l"(a), "l"(b)); return r;
}
__device__ __forceinline__ u64 fma2(u64 a, u64 b, u64 c) {
    u64 r; asm("fma.rn.f32x2 %0, %1, %2, %3;" : "=l"(r) : "l"(a), "l"(b), "l"(c)); return r;
}

__global__ void zero_kernel() {
    if (threadIdx.x < 4) d_acc[threadIdx.x] = 0.0;
}

// grid (4, BB) x 256: per-gaussian attribute compute + entropy partial
__global__ void prep_kernel(const float* __restrict__ g, const float* __restrict__ intr) {
    int b = blockIdx.y;
    int i = blockIdx.x * 256 + threadIdx.x;
    const float* gg = g + ((size_t)b * NN + i) * 38;
    float m0 = gg[0], m1 = gg[1], m2 = gg[2];
    float sx = gg[3], sy = gg[4], sz = gg[5];
    float qw = gg[6], qx = gg[7], qy = gg[8], qz = gg[9];
    float op = gg[10];
    float shr = gg[11], shg = gg[12], shb = gg[13];
    const float* I = intr + b * 9;
    float fx = I[0], cx = I[2], fy = I[4], cy = I[5];

    float zz = fmaxf(m2, 1e-4f);
    float px = fx * m0 / zz + cx;
    float py = fy * m1 / zz + cy;

    float R00 = 1.f - 2.f * (qy * qy + qz * qz), R01 = 2.f * (qx * qy - qw * qz), R02 = 2.f * (qx * qz + qw * qy);
    float R10 = 2.f * (qx * qy + qw * qz), R11 = 1.f - 2.f * (qx * qx + qz * qz), R12 = 2.f * (qy * qz - qw * qx);
    float R20 = 2.f * (qx * qz - qw * qy), R21 = 2.f * (qy * qz + qw * qx), R22 = 1.f - 2.f * (qx * qx + qy * qy);
    float A00 = R00 * sx, A01 = R01 * sy, A02 = R02 * sz;
    float A10 = R10 * sx, A11 = R11 * sy, A12 = R12 * sz;
    float A20 = R20 * sx, A21 = R21 * sy, A22 = R22 * sz;
    float C00 = A00 * A00 + A01 * A01 + A02 * A02;
    float C01 = A00 * A10 + A01 * A11 + A02 * A12;
    float C02 = A00 * A20 + A01 * A21 + A02 * A22;
    float C11 = A10 * A10 + A11 * A11 + A12 * A12;
    float C12 = A10 * A20 + A11 * A21 + A12 * A22;
    float C22 = A20 * A20 + A21 * A21 + A22 * A22;

    float zc = fmaxf(m2, 1e-6f);
    float zi = 1.f / zc, zi2 = zi * zi;
    float J00 = fx * zi, J02 = -fx * m0 * zi2;
    float J11 = fy * zi, J12 = -fy * m1 * zi2;
    float t0 = J00 * C00 + J02 * C02;
    float t1 = J00 * C01 + J02 * C12;
    float t2 = J00 * C02 + J02 * C22;
    float u0 = J11 * C01 + J12 * C02;
    float u1 = J11 * C11 + J12 * C12;
    float u2 = J11 * C12 + J12 * C22;
    float c00 = t0 * J00 + t2 * J02 + 0.3f;
    float c01 = t1 * J11 + t2 * J12;
    float c10 = u0 * J00 + u2 * J02;
    float c11 = u1 * J11 + u2 * J12 + 0.3f;
    float det = fmaxf(c00 * c11 - c01 * c10, 1e-8f);
    float inv00 = c11 / det, inv11 = c00 / det, inv01 = -c01 / det;

    const float C0c = 0.28209479177387814f;
    float cr = fminf(fmaxf(shr * C0c + 0.5f, 0.f), 1.f);
    float cg = fminf(fmaxf(shg * C0c + 0.5f, 0.f), 1.f);
    float cb = fminf(fmaxf(shb * C0c + 0.5f, 0.f), 1.f);

    const float L2E = 1.4426950408889634f;
    float4* dst = d_attr + ((size_t)b * NN + i) * 3;
    dst[0] = make_float4(-px, -py, -0.5f * inv00 * L2E, -inv01 * L2E);
    dst[1] = make_float4(-0.5f * inv11 * L2E, op, cr, cg);
    dst[2] = make_float4(cb, zz, 0.f, 0.f);
    d_z[b * NN + i] = zz;

    float o = fminf(fmaxf(op, 1e-6f), 1.f - 1e-6f);
    float ent = -(o * logf(o) + (1.f - o) * logf(1.f - o));

    __shared__ float red[8];
    float v = warp_sum(ent);
    int lane = threadIdx.x & 31, wid = threadIdx.x >> 5;
    if (lane == 0) red[wid] = v;
    __syncthreads();
    if (wid == 0) {
        float x = (lane < 8) ? red[lane] : 0.f;
        x = warp_sum(x);
        if (lane == 0) atomicAdd(&d_acc[3], (double)x);
    }
}

// grid (BB*8) x 128: stable rank by z + scatter attrs into sorted order
__global__ void rank_kernel() {
    int b = blockIdx.x >> 3;
    int s = blockIdx.x & 7;
    __shared__ float zs[NN];
    for (int k = threadIdx.x; k < NN; k += 128) zs[k] = d_z[b * NN + k];
    __syncthreads();
    int i = s * 128 + threadIdx.x;
    float zi = zs[i];
    int rank = 0;
#pragma unroll 8
    for (int j = 0; j < NN; j++) {
        float zj = zs[j];
        rank += (zj < zi) || (zj == zi && j < i);
    }
    const float4* src = d_attr + ((size_t)b * NN + i) * 3;
    float4* dst = d_sorted + ((size_t)b * NN + rank) * 3;
    dst[0] = src[0];
    dst[1] = src[1];
    dst[2] = src[2];
}

// grid (8, 8, BB*SEG) x 128; each thread composites 2 pixels (y, y+8) packed f32x2
__global__ void render_kernel() {
    int bz = blockIdx.z;
    int b = bz >> 3;       // SEG == 8
    int s = bz & 7;
    int t = threadIdx.x;
    int tx = t & 15, ty = t >> 4;
    int x = blockIdx.x * 16 + tx;
    int y0 = blockIdx.y * 16 + ty;          // second pixel at y0+8
    float xf = (float)x, yf0 = (float)y0, yf1 = (float)(y0 + 8);
    u64 xp = pk2(xf, xf);
    u64 yp = pk2(yf0, yf1);

    __shared__ float4 sg[GPS * 5];          // duplicated layout, 10KB
    const float4* base = d_sorted + ((size_t)b * NN + s * GPS) * 3;
    for (int k = t; k < GPS; k += 128) {
        float4 q0 = base[k * 3 + 0];
        float4 q1 = base[k * 3 + 1];
        float4 q2 = base[k * 3 + 2];
        sg[k * 5 + 0] = make_float4(q0.x, q0.x, q0.y, q0.y);   // npx2, npy2
        sg[k * 5 + 1] = make_float4(q0.z, q0.z, q0.w, q0.w);   // h002, h012
        sg[k * 5 + 2] = make_float4(q1.x, q1.x, q1.y, q1.y);   // h112, op2
        sg[k * 5 + 3] = make_float4(q1.z, q1.z, q1.w, q1.w);   // r2,   g2
        sg[k * 5 + 4] = make_float4(q2.x, q2.x, q2.y, q2.y);   // b2,   z2
    }
    __syncthreads();

    u64 T = pk2(1.f, 1.f);
    u64 aR = 0ull, aG = 0ull, aB = 0ull, aD = 0ull;
    const u64 onep = pk2(1.f, 1.f);
    const u64 negonep = pk2(-1.f, -1.f);
    const float CLMP = -14.4269504088896f;   // -10 * log2(e)

    const ulonglong2* sp = (const ulonglong2*)sg;
#pragma unroll 4
    for (int j = 0; j < GPS; j++) {
        ulonglong2 w0 = sp[j * 5 + 0];
        ulonglong2 w1 = sp[j * 5 + 1];
        ulonglong2 w2 = sp[j * 5 + 2];
        ulonglong2 w3 = sp[j * 5 + 3];
        ulonglong2 w4 = sp[j * 5 + 4];
        u64 dx = add2(xp, w0.x);
        u64 dy = add2(yp, w0.y);
        u64 t2 = mul2(w1.y, dy);           // h01*dy
        u64 uu = fma2(w1.x, dx, t2);       // h00*dx + h01*dy
        u64 t1 = mul2(w2.x, dy);           // h11*dy
        u64 t1b = mul2(t1, dy);            // h11*dy*dy
        u64 pw = fma2(dx, uu, t1b);        // log2-domain power (<= ~0)
        float p0, p1;
        upk2(p0, p1, pw);
        p0 = fmaxf(p0, CLMP);
        p1 = fmaxf(p1, CLMP);
        float e0, e1;
        asm("ex2.approx.f32 %0, %1;" : "=f"(e0) : "f"(p0));
        asm("ex2.approx.f32 %0, %1;" : "=f"(e1) : "f"(p1));
        u64 ep = pk2(e0, e1);
        u64 ap = mul2(ep, w2.y);           // * opacity
        float a0, a1;
        upk2(a0, a1, ap);
        a0 = fminf(a0, 0.99f);
        a1 = fminf(a1, 0.99f);
        u64 am = pk2(a0, a1);
        u64 onem = fma2(am, negonep, onep);    // 1 - a
        u64 w = mul2(T, am);
        T = mul2(T, onem);
        aR = fma2(w, w3.x, aR);
        aG = fma2(w, w3.y, aG);
        aB = fma2(w, w4.x, aB);
        aD = fma2(w, w4.y, aD);
    }

    float r0, r1, g0, g1, b0, b1, dd0, dd1, T0, T1;
    upk2(r0, r1, aR); upk2(g0, g1, aG); upk2(b0, b1, aB); upk2(dd0, dd1, aD); upk2(T0, T1, T);
    int segbase = (b * SEG + s) * (HH * WW);
    int o0 = segbase + y0 * WW + x;
    int o1 = segbase + (y0 + 8) * WW + x;
    d_seg_rgbd[o0] = make_float4(r0, g0, b0, dd0);
    d_seg_rgbd[o1] = make_float4(r1, g1, b1, dd1);
    d_seg_T[o0] = T0;
    d_seg_T[o1] = T1;
}

// grid 1024 x 256: one thread per (pixel, segment); 8-lane shuffle scan merge
__global__ void merge_kernel(const float* __restrict__ target_rgb,
                             const float* __restrict__ target_depth) {
    int idx = blockIdx.x * 256 + threadIdx.x;
    int s = idx & 7;
    int g = idx >> 3;
    int hw = HH * WW;
    int b = g / hw;
    int pix = g % hw;
    int o = (b * SEG + s) * hw + pix;
    float4 c = d_seg_rgbd[o];
    float t = d_seg_T[o];

    // inclusive prefix product of t within 8-lane group
    float pre = t;
    int sub = threadIdx.x & 7;
#pragma unroll
    for (int d = 1; d < 8; d <<= 1) {
        float v = __shfl_up_sync(0xffffffffu, pre, d, 8);
        if (sub >= d) pre *= v;
    }
    // exclusive prefix (transmittance before this segment)
    float Texc = __shfl_up_sync(0xffffffffu, pre, 1, 8);
    if (sub == 0) Texc = 1.f;
    c.x *= Texc; c.y *= Texc; c.z *= Texc; c.w *= Texc;
#pragma unroll
    for (int d = 4; d; d >>= 1) {
        c.x += __shfl_down_sync(0xffffffffu, c.x, d, 8);
        c.y += __shfl_down_sync(0xffffffffu, c.y, d, 8);
        c.z += __shfl_down_sync(0xffffffffu, c.z, d, 8);
        c.w += __shfl_down_sync(0xffffffffu, c.w, d, 8);
    }

    float l1 = 0.f, l1d = 0.f;
    if (sub == 0) {
        float R = fminf(fmaxf(c.x, 0.f), 1.f);
        float G = fminf(fmaxf(c.y, 0.f), 1.f);
        float Bc = fminf(fmaxf(c.z, 0.f), 1.f);
        d_rgb[(b * 3 + 0) * hw + pix] = R;
        d_rgb[(b * 3 + 1) * hw + pix] = G;
        d_rgb[(b * 3 + 2) * hw + pix] = Bc;
        l1 = fabsf(R - target_rgb[(b * 3 + 0) * hw + pix]) +
             fabsf(G - target_rgb[(b * 3 + 1) * hw + pix]) +
             fabsf(Bc - target_rgb[(b * 3 + 2) * hw + pix]);
        l1d = fabsf(c.w - target_depth[b * hw + pix]);
    }

    __shared__ float red[8];
    int lane = threadIdx.x & 31, wid = threadIdx.x >> 5;
    float v = warp_sum(l1);
    if (lane == 0) red[wid] = v;
    __syncthreads();
    if (wid == 0) {
        float sm = (lane < 8) ? red[lane] : 0.f;
        sm = warp_sum(sm);
        if (lane == 0) atomicAdd(&d_acc[0], (double)sm);
    }
    __syncthreads();
    v = warp_sum(l1d);
    if (lane == 0) red[wid] = v;
    __syncthreads();
    if (wid == 0) {
        float sm = (lane < 8) ? red[lane] : 0.f;
        sm = warp_sum(sm);
        if (lane == 0) atomicAdd(&d_acc[1], (double)sm);
    }
}

// fused 7x7 depthwise SSIM + mean reduce
__global__ void ssim_kernel(const float* __restrict__ target_rgb) {
    const float GW[7] = {0.03663229f, 0.11128005f, 0.21674607f, 0.27068313f,
                         0.21674607f, 0.11128005f, 0.03663229f};
    int idx = blockIdx.x * 256 + threadIdx.x;
    float val = 0.f;
    if (idx < BB * 3 * HH * WW) {
        int x = idx % WW;
        int y = (idx / WW) % HH;
        int bc = idx / (HH * WW);
        const float* i1 = d_rgb + (size_t)bc * HH * WW;
        const float* i2 = target_rgb + (size_t)bc * HH * WW;

        float m1 = 0.f, m2 = 0.f, e11 = 0.f, e22 = 0.f, e12 = 0.f;
        if (x >= 3 && x < WW - 3 && y >= 3 && y < HH - 3) {
#pragma unroll
            for (int ky = 0; ky < 7; ky++) {
                int yy = y + ky - 3;
                float wy = GW[ky];
#pragma unroll
                for (int kx = 0; kx < 7; kx++) {
                    int xx = x + kx - 3;
                    float w = wy * GW[kx];
                    float v1 = i1[yy * WW + xx];
                    float v2 = i2[yy * WW + xx];
                    m1 = fmaf(w, v1, m1);
                    m2 = fmaf(w, v2, m2);
                    e11 = fmaf(w * v1, v1, e11);
                    e22 = fmaf(w * v2, v2, e22);
                    e12 = fmaf(w * v1, v2, e12);
                }
            }
        } else {
#pragma unroll
            for (int ky = 0; ky < 7; ky++) {
                int yy = y + ky - 3;
                if (yy < 0 || yy >= HH) continue;
                float wy = GW[ky];
#pragma unroll
                for (int kx = 0; kx < 7; kx++) {
                    int xx = x + kx - 3;
                    if (xx < 0 || xx >= WW) continue;
                    float w = wy * GW[kx];
                    float v1 = i1[yy * WW + xx];
                    float v2 = i2[yy * WW + xx];
                    m1 = fmaf(w, v1, m1);
                    m2 = fmaf(w, v2, m2);
                    e11 = fmaf(w * v1, v1, e11);
                    e22 = fmaf(w * v2, v2, e22);
                    e12 = fmaf(w * v1, v2, e12);
                }
            }
        }
        float s1 = e11 - m1 * m1;
        float s2 = e22 - m2 * m2;
        float s12 = e12 - m1 * m2;
        const float C1 = 0.0001f, C2 = 0.0009f;
        val = (2.f * m1 * m2 + C1) * (2.f * s12 + C2) /
              ((m1 * m1 + m2 * m2 + C1) * (s1 + s2 + C2));
    }
    __shared__ float red[8];
    int lane = threadIdx.x & 31, wid = threadIdx.x >> 5;
    float v = warp_sum(val);
    if (lane == 0) red[wid] = v;
    __syncthreads();
    if (wid == 0) {
        float x2 = (lane < 8) ? red[lane] : 0.f;
        x2 = warp_sum(x2);
        if (lane == 0) atomicAdd(&d_acc[2], (double)x2);
    }
}

__global__ void final_kernel(float* __restrict__ out) {
    double l1rgb = d_acc[0] / (double)(BB * 3 * HH * WW);
    double l1d = d_acc[1] / (double)(BB * HH * WW);
    double ssim = d_acc[2] / (double)(BB * 3 * HH * WW);
    double opac = d_acc[3] / (double)(BB * NN);
    out[0] = (float)(0.8 * l1rgb + 0.2 * (1.0 - ssim) + 0.5 * l1d + 0.01 * opac);
}

extern "C" void kernel_launch(void* const* d_in, const int* in_sizes, int n_in,
                              void* d_out, int out_size) {
    const float* gaussians = (const float*)d_in[0];
    const float* intrinsics = (const float*)d_in[1];
    const float* target_rgb = (const float*)d_in[2];
    const float* target_depth = (const float*)d_in[3];
    float* out = (float*)d_out;

    zero_kernel<<<1, 32>>>();
    prep_kernel<<<dim3(4, BB), 256>>>(gaussians, intrinsics);
    rank_kernel<<<BB * 8, 128>>>();
    render_kernel<<<dim3(8, 8, BB * SEG), 128>>>();
    merge_kernel<<<(BB * HH * WW * SEG) / 256, 256>>>(target_rgb, target_depth);
    ssim_kernel<<<(BB * 3 * HH * WW + 255) / 256, 256>>>(target_rgb);
    final_kernel<<<1, 1>>>(out);
}